// round 1
// baseline (speedup 1.0000x reference)
#include <cuda_runtime.h>

// ---------------------------------------------------------------------------
// dsfa_former: (1) full causal attention + (2) Linformer attention
// Shapes (fixed): B=4, N=2048, H=8, D=32, KP=256
// Inputs: queries, keys, values [B,N,H,D] f32; E_proj, F_proj [N,KP] f32
// Output: concat(out_full, out_lin), each [B,N,H,D] f32
// ---------------------------------------------------------------------------

constexpr int B  = 4;
constexpr int N  = 2048;
constexpr int H  = 8;
constexpr int D  = 32;
constexpr int KP = 256;

constexpr int ROW  = H * D;        // 256 floats per (b,n) row
constexpr int ROW4 = ROW / 4;      // 64 float4
constexpr int OUT_HALF = B * N * H * D;  // 2097152

// scratch (no cudaMalloc allowed)
__device__ float g_partial[8 * 2 * 32 * KP * D];  // [chunk][mat][bh][kk][e]  16 MB
__device__ float g_kpvp[2 * 32 * KP * D];         // [mat][bh][kk][e]          2 MB

__device__ __forceinline__ float dot4(float4 a, float4 b) {
    return fmaf(a.x, b.x, fmaf(a.y, b.y, fmaf(a.z, b.z, a.w * b.w)));
}
__device__ __forceinline__ float4 fma4(float s, float4 a, float4 c) {
    c.x = fmaf(s, a.x, c.x); c.y = fmaf(s, a.y, c.y);
    c.z = fmaf(s, a.z, c.z); c.w = fmaf(s, a.w, c.w);
    return c;
}
__device__ __forceinline__ float4 scl4(float4 a, float s) {
    a.x *= s; a.y *= s; a.z *= s; a.w *= s; return a;
}

// ---------------------------------------------------------------------------
// Kernel 1: full causal attention. 1 thread = 1 query row.
// grid.x = 256 blocks: bid -> (qt = 7 - bid/32 [heavy first], bh = bid%32)
// ---------------------------------------------------------------------------
__global__ void __launch_bounds__(256, 2)
full_attn_kernel(const float* __restrict__ Q, const float* __restrict__ K,
                 const float* __restrict__ V, float* __restrict__ out)
{
    __shared__ float4 Ks[128 * 8];
    __shared__ float4 Vs[128 * 8];

    const int bid = blockIdx.x;
    const int qt  = 7 - (bid >> 5);   // heavy diagonal blocks scheduled first
    const int bh  = bid & 31;
    const int b   = bh >> 3, h = bh & 7;
    const int tid = threadIdx.x;
    const int i   = qt * 256 + tid;
    const float scale = 0.17677669529663687f;  // 1/sqrt(32)

    const size_t base = (size_t)b * N * ROW + (size_t)h * D;
    const float4* Qg = (const float4*)(Q + base);
    const float4* Kg = (const float4*)(K + base);
    const float4* Vg = (const float4*)(V + base);

    const size_t qoff = (size_t)i * ROW4;
    float4 q0 = Qg[qoff+0], q1 = Qg[qoff+1], q2 = Qg[qoff+2], q3 = Qg[qoff+3];
    float4 q4 = Qg[qoff+4], q5 = Qg[qoff+5], q6 = Qg[qoff+6], q7 = Qg[qoff+7];

    float4 a0 = make_float4(0,0,0,0), a1 = a0, a2 = a0, a3 = a0;
    float4 a4 = a0, a5 = a0, a6 = a0, a7 = a0;
    float m = -1e30f, l = 0.f;

    const int ntiles = 2 * qt + 2;
    for (int kt = 0; kt < ntiles; ++kt) {
        const int j0 = kt * 128;
        // cooperative tile load: 128 rows x 8 float4
        for (int f = tid; f < 1024; f += 256) {
            const int r = f >> 3, c = f & 7;
            const size_t g = (size_t)(j0 + r) * ROW4 + c;
            Ks[f] = Kg[g];
            Vs[f] = Vg[g];
        }
        __syncthreads();

        int jmax = i - j0 + 1;               // exact causal bound per thread
        if (jmax > 128) jmax = 128;
        for (int jj = 0; jj < jmax; ++jj) {
            const float4* kr = &Ks[jj * 8];
            float s01 = dot4(q0, kr[0]) + dot4(q1, kr[1]);
            float s23 = dot4(q2, kr[2]) + dot4(q3, kr[3]);
            float s45 = dot4(q4, kr[4]) + dot4(q5, kr[5]);
            float s67 = dot4(q6, kr[6]) + dot4(q7, kr[7]);
            const float sl = ((s01 + s23) + (s45 + s67)) * scale;
            if (sl > m) {                     // rare rescale (running max)
                const float c = __expf(m - sl);
                m = sl; l *= c;
                a0 = scl4(a0,c); a1 = scl4(a1,c); a2 = scl4(a2,c); a3 = scl4(a3,c);
                a4 = scl4(a4,c); a5 = scl4(a5,c); a6 = scl4(a6,c); a7 = scl4(a7,c);
            }
            const float p = __expf(sl - m);
            l += p;
            const float4* vr = &Vs[jj * 8];
            a0 = fma4(p, vr[0], a0); a1 = fma4(p, vr[1], a1);
            a2 = fma4(p, vr[2], a2); a3 = fma4(p, vr[3], a3);
            a4 = fma4(p, vr[4], a4); a5 = fma4(p, vr[5], a5);
            a6 = fma4(p, vr[6], a6); a7 = fma4(p, vr[7], a7);
        }
        __syncthreads();
    }

    const float inv = 1.0f / l;
    float4* Og = (float4*)(out + base);
    Og[qoff+0] = scl4(a0, inv); Og[qoff+1] = scl4(a1, inv);
    Og[qoff+2] = scl4(a2, inv); Og[qoff+3] = scl4(a3, inv);
    Og[qoff+4] = scl4(a4, inv); Og[qoff+5] = scl4(a5, inv);
    Og[qoff+6] = scl4(a6, inv); Og[qoff+7] = scl4(a7, inv);
}

// ---------------------------------------------------------------------------
// Kernel 2: Linformer projections Kp = E^T K_b, Vp = F^T V_b.
// grid (bh=32, mat=2, chunk=8); thread = kk; partial sums over n-chunk of 256.
// ---------------------------------------------------------------------------
__global__ void __launch_bounds__(256)
proj_kernel(const float* __restrict__ K, const float* __restrict__ V,
            const float* __restrict__ E, const float* __restrict__ F)
{
    __shared__ float4 Xs[64 * 8];
    const int bh = blockIdx.x, mat = blockIdx.y, chunk = blockIdx.z;
    const int b = bh >> 3, h = bh & 7;
    const int kk = threadIdx.x;

    const float* X = mat ? V : K;
    const float* P = mat ? F : E;
    const float4* Xg = (const float4*)(X + (size_t)b * N * ROW + (size_t)h * D);

    float4 acc[8];
#pragma unroll
    for (int r = 0; r < 8; ++r) acc[r] = make_float4(0,0,0,0);

    for (int t = 0; t < 4; ++t) {
        const int n0 = chunk * 256 + t * 64;
        for (int f = threadIdx.x; f < 512; f += 256) {
            const int r = f >> 3, c = f & 7;
            Xs[f] = Xg[(size_t)(n0 + r) * ROW4 + c];
        }
        __syncthreads();
#pragma unroll 4
        for (int nn = 0; nn < 64; ++nn) {
            const float ev = __ldg(&P[(size_t)(n0 + nn) * KP + kk]);  // coalesced
            const float4* xr = &Xs[nn * 8];
#pragma unroll
            for (int r = 0; r < 8; ++r) acc[r] = fma4(ev, xr[r], acc[r]);
        }
        __syncthreads();
    }

    float4* pp = (float4*)g_partial +
                 ((size_t)((chunk * 2 + mat) * 32 + bh) * KP + kk) * 8;
#pragma unroll
    for (int r = 0; r < 8; ++r) pp[r] = acc[r];
}

// ---------------------------------------------------------------------------
// Kernel 2b: reduce the 8 n-chunks -> g_kpvp[mat][bh][kk][e]
// ---------------------------------------------------------------------------
__global__ void reduce_kernel()
{
    const int idx = blockIdx.x * 256 + threadIdx.x;   // 131072 float4
    const float4* p = (const float4*)g_partial;
    float4 s = p[idx];
#pragma unroll
    for (int c = 1; c < 8; ++c) {
        const float4 t = p[(size_t)c * 131072 + idx];
        s.x += t.x; s.y += t.y; s.z += t.z; s.w += t.w;
    }
    ((float4*)g_kpvp)[idx] = s;
}

// ---------------------------------------------------------------------------
// Kernel 3: Linformer attention. 1 thread = 1 query row, 256 projected keys.
// grid (bh=32, ntile=8); Kp/Vp staged in smem in two 128-key halves.
// ---------------------------------------------------------------------------
__global__ void __launch_bounds__(256, 2)
lin_attn_kernel(const float* __restrict__ Q, float* __restrict__ out)
{
    __shared__ float4 Kps[128 * 8];
    __shared__ float4 Vps[128 * 8];

    const int bh = blockIdx.x, nt = blockIdx.y;
    const int b = bh >> 3, h = bh & 7;
    const int tid = threadIdx.x;
    const int n = nt * 256 + tid;
    const float scale = 0.17677669529663687f;

    const size_t base = (size_t)b * N * ROW + (size_t)h * D;
    const float4* Qg  = (const float4*)(Q + base);
    const float4* Kpg = (const float4*)g_kpvp + (size_t)bh * (KP * 8);
    const float4* Vpg = (const float4*)g_kpvp + (size_t)(32 + bh) * (KP * 8);

    const size_t qoff = (size_t)n * ROW4;
    float4 q0 = Qg[qoff+0], q1 = Qg[qoff+1], q2 = Qg[qoff+2], q3 = Qg[qoff+3];
    float4 q4 = Qg[qoff+4], q5 = Qg[qoff+5], q6 = Qg[qoff+6], q7 = Qg[qoff+7];

    float4 a0 = make_float4(0,0,0,0), a1 = a0, a2 = a0, a3 = a0;
    float4 a4 = a0, a5 = a0, a6 = a0, a7 = a0;
    float m = -1e30f, l = 0.f;

    for (int half = 0; half < 2; ++half) {
        for (int f = tid; f < 1024; f += 256) {
            Kps[f] = Kpg[half * 1024 + f];
            Vps[f] = Vpg[half * 1024 + f];
        }
        __syncthreads();
        for (int kk = 0; kk < 128; ++kk) {
            const float4* kr = &Kps[kk * 8];
            float s01 = dot4(q0, kr[0]) + dot4(q1, kr[1]);
            float s23 = dot4(q2, kr[2]) + dot4(q3, kr[3]);
            float s45 = dot4(q4, kr[4]) + dot4(q5, kr[5]);
            float s67 = dot4(q6, kr[6]) + dot4(q7, kr[7]);
            const float sl = ((s01 + s23) + (s45 + s67)) * scale;
            if (sl > m) {
                const float c = __expf(m - sl);
                m = sl; l *= c;
                a0 = scl4(a0,c); a1 = scl4(a1,c); a2 = scl4(a2,c); a3 = scl4(a3,c);
                a4 = scl4(a4,c); a5 = scl4(a5,c); a6 = scl4(a6,c); a7 = scl4(a7,c);
            }
            const float p = __expf(sl - m);
            l += p;
            const float4* vr = &Vps[kk * 8];
            a0 = fma4(p, vr[0], a0); a1 = fma4(p, vr[1], a1);
            a2 = fma4(p, vr[2], a2); a3 = fma4(p, vr[3], a3);
            a4 = fma4(p, vr[4], a4); a5 = fma4(p, vr[5], a5);
            a6 = fma4(p, vr[6], a6); a7 = fma4(p, vr[7], a7);
        }
        __syncthreads();
    }

    const float inv = 1.0f / l;
    float4* Og = (float4*)(out + base);
    Og[qoff+0] = scl4(a0, inv); Og[qoff+1] = scl4(a1, inv);
    Og[qoff+2] = scl4(a2, inv); Og[qoff+3] = scl4(a3, inv);
    Og[qoff+4] = scl4(a4, inv); Og[qoff+5] = scl4(a5, inv);
    Og[qoff+6] = scl4(a6, inv); Og[qoff+7] = scl4(a7, inv);
}

// ---------------------------------------------------------------------------
extern "C" void kernel_launch(void* const* d_in, const int* in_sizes, int n_in,
                              void* d_out, int out_size)
{
    const float* Q = (const float*)d_in[0];
    const float* K = (const float*)d_in[1];
    const float* V = (const float*)d_in[2];
    const float* E = (const float*)d_in[3];
    const float* F = (const float*)d_in[4];
    float* out = (float*)d_out;

    proj_kernel<<<dim3(32, 2, 8), 256>>>(K, V, E, F);
    reduce_kernel<<<512, 256>>>();
    full_attn_kernel<<<256, 256>>>(Q, K, V, out);            // out_full
    lin_attn_kernel<<<dim3(32, 8), 256>>>(Q, out + OUT_HALF); // out_lin
}